// round 15
// baseline (speedup 1.0000x reference)
#include <cuda_runtime.h>
#include <cuda_bf16.h>
#include <cuda_fp16.h>
#include <math.h>

#define N_NODES 50000
#define N_EDGES 600000
#define D 128
#define N_RELS 460

#define DEG_PAD 53248               // 13 blocks * 1024 threads * 4 items
#define SCAN_BLOCKS 13
#define COUNT_BLOCKS 586            // ceil(N_EDGES/1024), 4 edges/thread
#define WSPLIT_BLOCKS 16            // 4096 fragment uint4s / 256
#define U_BLOCKS 2                  // 384 u-outputs / 256
#define SCORE_BLOCKS 50             // ceil((N_NODES+N_RELS)/1024)
#define GEMM_BLOCKS 782             // ceil(N_NODES/64)

// ---------------- device scratch ----------------
__device__ __align__(16) int g_deg[DEG_PAD];
__device__ __align__(16) int g_off[DEG_PAD];     // exclusive prefix (padded; [N_NODES] valid)
__device__ int   g_scan_pub[SCAN_BLOCKS];        // inclusive+1; 0 = not ready
__device__ __align__(16) float g_u[3 * D];       // collapsed attention vector
__device__ float g_s_src[N_NODES];
__device__ float g_s_dst[N_NODES];
__device__ float g_s_rel[N_RELS];
__device__ __align__(8) uint2 g_edge[N_EDGES];   // {exp(score) bits, src}, grouped by dst
__device__ __align__(16) uint2 g_hh[N_NODES * 32]; // h in fp16, 8B/lane (12.8 MB, L2-res)
// W^T in HMMA b-fragment order: [ntile(16)][ks(8)][lane(32)] = {bhi0,bhi1,blo0,blo1}
__device__ __align__(16) uint4 g_wfrag[16 * 8 * 32];

// ---------------- HMMA m16n8k16 bf16, fp32 acc ----------------
#define MMA16816(d, a, b0, b1)                                                  \
    asm volatile("mma.sync.aligned.m16n8k16.row.col.f32.bf16.bf16.f32 "         \
        "{%0,%1,%2,%3}, {%4,%5,%6,%7}, {%8,%9}, {%0,%1,%2,%3};"                 \
        : "+f"((d)[0]), "+f"((d)[1]), "+f"((d)[2]), "+f"((d)[3])                \
        : "r"((a)[0]), "r"((a)[1]), "r"((a)[2]), "r"((a)[3]),                   \
          "r"(b0), "r"(b1))

#define LDSM4(r, a)                                                             \
    asm volatile("ldmatrix.sync.aligned.m8n8.x4.shared.b16 {%0,%1,%2,%3}, [%4];" \
        : "=r"((r)[0]), "=r"((r)[1]), "=r"((r)[2]), "=r"((r)[3]) : "r"(a))

__device__ __forceinline__ unsigned smem_u32(const void* p) {
    unsigned a;
    asm("{ .reg .u64 t; cvta.to.shared.u64 t, %1; cvt.u32.u64 %0, t; }" : "=r"(a) : "l"(p));
    return a;
}
__device__ __forceinline__ unsigned pack_hi(float a, float b) {
    __nv_bfloat162 v = __floats2bfloat162_rn(a, b);
    return *(unsigned*)&v;
}
__device__ __forceinline__ float4 h4_to_f4(uint2 p) {
    __half2 lo = *reinterpret_cast<__half2*>(&p.x);
    __half2 hi = *reinterpret_cast<__half2*>(&p.y);
    float2 a = __half22float2(lo), b = __half22float2(hi);
    return make_float4(a.x, a.y, b.x, b.y);
}
__device__ __forceinline__ uint2 f4_to_h4(float4 v) {
    __half2 q01 = __floats2half2_rn(v.x, v.y);
    __half2 q23 = __floats2half2_rn(v.z, v.w);
    return make_uint2(*(unsigned*)&q01, *(unsigned*)&q23);
}

// ============================================================================
// K1: degree count + W fragment-split + u-compute + scan-flag reset.
// ============================================================================
__global__ void k_prep(const float* __restrict__ W,
                       const float* __restrict__ w2,
                       const int*   __restrict__ edst,
                       const float* __restrict__ loopW) {
    if (blockIdx.x < COUNT_BLOCKS) {
        int i4 = blockIdx.x * 256 + threadIdx.x;
        if (i4 * 4 < N_EDGES) {
            int4 d4 = ((const int4*)edst)[i4];
            atomicAdd(&g_deg[d4.x], 1);
            atomicAdd(&g_deg[d4.y], 1);
            atomicAdd(&g_deg[d4.z], 1);
            atomicAdd(&g_deg[d4.w], 1);
        }
    } else if (blockIdx.x < COUNT_BLOCKS + WSPLIT_BLOCKS) {
        // W -> HMMA b-fragment table (+ scan-flag reset)
        int gid = (blockIdx.x - COUNT_BLOCKS) * 256 + threadIdx.x;
        if (gid < SCAN_BLOCKS) g_scan_pub[gid] = 0;
        int ntile = gid >> 8;            // 0..15
        int ks    = (gid >> 5) & 7;      // 0..7
        int lane  = gid & 31;
        int g = lane >> 2, t = lane & 3;
        int n  = ntile * 8 + g;
        int k0 = ks * 16 + 2 * t;
        float w00 = loopW[k0 * D + n];
        float w01 = loopW[(k0 + 1) * D + n];
        float w80 = loopW[(k0 + 8) * D + n];
        float w81 = loopW[(k0 + 9) * D + n];
        unsigned hi0 = pack_hi(w00, w01);
        unsigned hi1 = pack_hi(w80, w81);
        __nv_bfloat162 h0 = *(__nv_bfloat162*)&hi0;
        __nv_bfloat162 h1 = *(__nv_bfloat162*)&hi1;
        unsigned lo0 = pack_hi(w00 - __bfloat162float(__low2bfloat16(h0)),
                               w01 - __bfloat162float(__high2bfloat16(h0)));
        unsigned lo1 = pack_hi(w80 - __bfloat162float(__low2bfloat16(h1)),
                               w81 - __bfloat162float(__high2bfloat16(h1)));
        g_wfrag[gid] = make_uint4(hi0, hi1, lo0, lo1);
    } else {
        // u = attn_fc_w.T @ attn_fc2_w  (384 outputs, computed once)
        int i = (blockIdx.x - COUNT_BLOCKS - WSPLIT_BLOCKS) * 256 + threadIdx.x;
        if (i < 3 * D) {
            float s = 0.f;
            #pragma unroll 16
            for (int o = 0; o < D; o++) s += w2[o] * W[o * (3 * D) + i];
            g_u[i] = s;
        }
    }
}

// ============================================================================
// K2: co-launched scan (blocks [0,13)) and node/rel scalar scores (rest).
// ============================================================================
__global__ void __launch_bounds__(1024) k_scan_scores(const float* __restrict__ h,
                                                      const float* __restrict__ emb_rel) {
    if (blockIdx.x < SCAN_BLOCKS) {
        // ---- decoupled-lookback exclusive scan, 1024 thr x 4 items ----
        __shared__ int sm[1024];
        __shared__ int s_prefix;
        int b = blockIdx.x, t = threadIdx.x;
        int4 v = ((const int4*)g_deg)[b * 1024 + t];
        int tot = v.x + v.y + v.z + v.w;
        sm[t] = tot;
        __syncthreads();
        #pragma unroll
        for (int off = 1; off < 1024; off <<= 1) {
            int val = (t >= off) ? sm[t - off] : 0;
            __syncthreads();
            sm[t] += val;
            __syncthreads();
        }
        if (t == 1023) {
            int inc = sm[1023];
            int p = 0;
            if (b > 0) {
                volatile int* pub = g_scan_pub;
                int x;
                do { x = pub[b - 1]; } while (x == 0);
                p = x - 1;
            }
            ((volatile int*)g_scan_pub)[b] = p + inc + 1;
            s_prefix = p;
        }
        __syncthreads();
        int pre = s_prefix + sm[t] - tot;
        int4 o;
        o.x = pre;
        o.y = pre + v.x;
        o.z = o.y + v.y;
        o.w = o.z + v.z;
        ((int4*)g_off)[b * 1024 + t] = o;
    } else {
        // ---- scores: each warp handles 32 units; u loaded from global ----
        int t = threadIdx.x;
        int lane = t & 31;
        int wid  = t >> 5;
        float4 u0 = ((const float4*)g_u)[lane];        // u_s
        float4 u1 = ((const float4*)g_u)[32 + lane];   // u_t
        float4 u2 = ((const float4*)g_u)[64 + lane];   // u_r
        int base = ((blockIdx.x - SCAN_BLOCKS) * 32 + wid) * 32;
        #pragma unroll 4
        for (int i = 0; i < 32; i++) {
            int gw = base + i;
            if (gw < N_NODES) {
                float4 hv = ((const float4*)h)[gw * 32 + lane];
                float ss = hv.x * u0.x + hv.y * u0.y + hv.z * u0.z + hv.w * u0.w;
                float sd = hv.x * u1.x + hv.y * u1.y + hv.z * u1.z + hv.w * u1.w;
                #pragma unroll
                for (int o = 16; o; o >>= 1) {
                    ss += __shfl_xor_sync(0xffffffffu, ss, o);
                    sd += __shfl_xor_sync(0xffffffffu, sd, o);
                }
                if (lane == 0) { g_s_src[gw] = ss; g_s_dst[gw] = sd; }
            } else if (gw < N_NODES + N_RELS) {
                int r = gw - N_NODES;
                float4 rv = ((const float4*)emb_rel)[r * 32 + lane];
                float sr = rv.x * u2.x + rv.y * u2.y + rv.z * u2.z + rv.w * u2.w;
                #pragma unroll
                for (int o = 16; o; o >>= 1) sr += __shfl_xor_sync(0xffffffffu, sr, o);
                if (lane == 0) g_s_rel[r] = sr;
            }
        }
    }
}

// ============================================================================
// K3: MERGED independent work: HMMA GEMM tile (blocks [0,782)) and
//     edge fill (blocks [782, 782+586)).
//   GEMM prologue also emits the fp16 copy of h (h already in registers).
// ============================================================================
#define A_STRIDE 272                        // 17*16: 16B-aligned rows
#define SM_A_HI  0
#define SM_A_LO  (64 * A_STRIDE)            // 17408
#define GEMM_SMEM (2 * 64 * A_STRIDE)       // 34816

__global__ void __launch_bounds__(256) k_gemm_fill(const float* __restrict__ h,
                                                   float* __restrict__ out,
                                                   const int* __restrict__ esrc,
                                                   const int* __restrict__ edst,
                                                   const int* __restrict__ etype) {
    extern __shared__ char smc[];
    int tid = threadIdx.x;

    if (blockIdx.x >= GEMM_BLOCKS) {
        // ================= edge fill =================
        int i4 = (blockIdx.x - GEMM_BLOCKS) * 256 + tid;
        if (i4 * 4 >= N_EDGES) return;
        int4 s4 = ((const int4*)esrc)[i4];
        int4 d4 = ((const int4*)edst)[i4];
        int4 t4 = ((const int4*)etype)[i4];
        #pragma unroll
        for (int j = 0; j < 4; j++) {
            int s = (j == 0) ? s4.x : (j == 1) ? s4.y : (j == 2) ? s4.z : s4.w;
            int d = (j == 0) ? d4.x : (j == 1) ? d4.y : (j == 2) ? d4.z : d4.w;
            int r = (j == 0) ? t4.x : (j == 1) ? t4.y : (j == 2) ? t4.z : t4.w;
            float e = g_s_src[s] + g_s_dst[d] + g_s_rel[r];
            e = (e >= 0.f) ? e : 0.01f * e;
            int pos = g_off[d] + (atomicSub(&g_deg[d], 1) - 1);
            g_edge[pos] = make_uint2(__float_as_uint(__expf(e)), (unsigned)s);
        }
        return;
    }

    // ================= GEMM (round-7 validated path) =================
    unsigned sb = smem_u32(smc);
    int lane = tid & 31, wid = tid >> 5;
    int row0 = blockIdx.x * 64;

    #pragma unroll
    for (int i = 0; i < 8; i++) {
        int idx = tid + i * 256;
        int r = idx >> 5, c4 = idx & 31;
        int row = row0 + r;
        float4 v = (row < N_NODES) ? ((const float4*)h)[row * 32 + c4]
                                   : make_float4(0.f, 0.f, 0.f, 0.f);
        // fp16 copy for the aggregate gather (h already in registers; coalesced 8B store)
        if (row < N_NODES) g_hh[row * 32 + c4] = f4_to_h4(v);
        __nv_bfloat162 h01 = __floats2bfloat162_rn(v.x, v.y);
        __nv_bfloat162 h23 = __floats2bfloat162_rn(v.z, v.w);
        float lx = v.x - __bfloat162float(__low2bfloat16(h01));
        float ly = v.y - __bfloat162float(__high2bfloat16(h01));
        float lz = v.z - __bfloat162float(__low2bfloat16(h23));
        float lw = v.w - __bfloat162float(__high2bfloat16(h23));
        __nv_bfloat162 l01 = __floats2bfloat162_rn(lx, ly);
        __nv_bfloat162 l23 = __floats2bfloat162_rn(lz, lw);
        unsigned off = r * A_STRIDE + c4 * 8;
        *(uint2*)(smc + SM_A_HI + off) = make_uint2(*(unsigned*)&h01, *(unsigned*)&h23);
        *(uint2*)(smc + SM_A_LO + off) = make_uint2(*(unsigned*)&l01, *(unsigned*)&l23);
    }
    __syncthreads();

    int g = lane >> 2, t = lane & 3;
    int wm = (wid & 1) * 32;
    int wn = (wid >> 1) * 32;

    unsigned aAddr = sb + SM_A_HI + (wm + (lane & 15)) * A_STRIDE + (lane >> 4) * 16;
    const uint4* __restrict__ wf = g_wfrag + (wn >> 3) * 256 + lane;

    float acc[2][4][4];
    #pragma unroll
    for (int a = 0; a < 2; a++)
        #pragma unroll
        for (int b2 = 0; b2 < 4; b2++)
            #pragma unroll
            for (int c = 0; c < 4; c++) acc[a][b2][c] = 0.f;

    #pragma unroll
    for (int ks = 0; ks < 8; ks++) {
        unsigned ahi[2][4], alo[2][4];
        #pragma unroll
        for (int mt = 0; mt < 2; mt++) {
            unsigned addr = aAddr + mt * (16 * A_STRIDE) + ks * 32;
            LDSM4(ahi[mt], addr);
            LDSM4(alo[mt], addr + (unsigned)SM_A_LO);
        }
        #pragma unroll
        for (int nt = 0; nt < 4; nt++) {
            uint4 f = wf[nt * 256 + ks * 32];
            #pragma unroll
            for (int mt = 0; mt < 2; mt++) {
                MMA16816(acc[mt][nt], ahi[mt], f.x, f.y);
                MMA16816(acc[mt][nt], ahi[mt], f.z, f.w);
                MMA16816(acc[mt][nt], alo[mt], f.x, f.y);
            }
        }
    }

    #pragma unroll
    for (int mt = 0; mt < 2; mt++) {
        int r0 = row0 + wm + mt * 16 + g;
        #pragma unroll
        for (int nt = 0; nt < 4; nt++) {
            int col = wn + nt * 8 + 2 * t;
            if (r0 < N_NODES)
                *(float2*)(out + r0 * D + col) = make_float2(acc[mt][nt][0], acc[mt][nt][1]);
            if (r0 + 8 < N_NODES)
                *(float2*)(out + (r0 + 8) * D + col) = make_float2(acc[mt][nt][2], acc[mt][nt][3]);
        }
    }
}

// ============================================================================
// K4: per-dst softmax-weighted gather-sum over the fp16 h table.
// ============================================================================
__global__ void k_aggregate(float* __restrict__ out) {
    int lane = threadIdx.x & 31;
    int n = blockIdx.x * 8 + (threadIdx.x >> 5);
    if (n >= N_NODES) return;
    int beg = g_off[n], end = g_off[n + 1];
    if (beg == end) return;

    float4 acc = {0.f, 0.f, 0.f, 0.f};
    float den = 0.f;
    int j = beg;
    for (; j + 4 <= end; j += 4) {
        uint2 e0 = g_edge[j],     e1 = g_edge[j + 1];
        uint2 e2 = g_edge[j + 2], e3 = g_edge[j + 3];
        uint2 p0 = g_hh[e0.y * 32 + lane];
        uint2 p1 = g_hh[e1.y * 32 + lane];
        uint2 p2 = g_hh[e2.y * 32 + lane];
        uint2 p3 = g_hh[e3.y * 32 + lane];
        float4 h0 = h4_to_f4(p0), h1 = h4_to_f4(p1);
        float4 h2 = h4_to_f4(p2), h3 = h4_to_f4(p3);
        float x0 = __uint_as_float(e0.x), x1 = __uint_as_float(e1.x);
        float x2 = __uint_as_float(e2.x), x3 = __uint_as_float(e3.x);
        den += (x0 + x1) + (x2 + x3);
        acc.x += x0 * h0.x + x1 * h1.x + x2 * h2.x + x3 * h3.x;
        acc.y += x0 * h0.y + x1 * h1.y + x2 * h2.y + x3 * h3.y;
        acc.z += x0 * h0.z + x1 * h1.z + x2 * h2.z + x3 * h3.z;
        acc.w += x0 * h0.w + x1 * h1.w + x2 * h2.w + x3 * h3.w;
    }
    for (; j < end; j++) {
        uint2 e0 = g_edge[j];
        float4 h0 = h4_to_f4(g_hh[e0.y * 32 + lane]);
        float x0 = __uint_as_float(e0.x);
        den += x0;
        acc.x += x0 * h0.x; acc.y += x0 * h0.y;
        acc.z += x0 * h0.z; acc.w += x0 * h0.w;
    }
    float inv = 1.f / den;
    float4* op = (float4*)out + n * 32 + lane;
    float4 o = *op;
    o.x += acc.x * inv; o.y += acc.y * inv;
    o.z += acc.z * inv; o.w += acc.w * inv;
    *op = o;
}

// ---------------- launch ----------------
extern "C" void kernel_launch(void* const* d_in, const int* in_sizes, int n_in,
                              void* d_out, int out_size) {
    const float* h          = (const float*)d_in[0];
    const float* emb_rel    = (const float*)d_in[1];
    const float* attn_fc_w  = (const float*)d_in[2];
    const float* attn_fc2_w = (const float*)d_in[3];
    const float* loop_w     = (const float*)d_in[4];
    const int*   esrc       = (const int*)d_in[5];
    const int*   edst       = (const int*)d_in[6];
    const int*   etype      = (const int*)d_in[7];
    float* out = (float*)d_out;

    cudaFuncSetAttribute(k_gemm_fill, cudaFuncAttributeMaxDynamicSharedMemorySize, GEMM_SMEM);

    k_prep<<<COUNT_BLOCKS + WSPLIT_BLOCKS + U_BLOCKS, 256>>>(attn_fc_w, attn_fc2_w, edst, loop_w);
    k_scan_scores<<<SCAN_BLOCKS + SCORE_BLOCKS, 1024>>>(h, emb_rel);
    k_gemm_fill<<<GEMM_BLOCKS + COUNT_BLOCKS, 256, GEMM_SMEM>>>(h, out, esrc, edst, etype);
    k_aggregate<<<(N_NODES + 7) / 8, 256>>>(out);
}

// round 16
// speedup vs baseline: 1.1157x; 1.1157x over previous
#include <cuda_runtime.h>
#include <cuda_bf16.h>
#include <math.h>

#define N_NODES 50000
#define N_EDGES 600000
#define D 128
#define N_RELS 460

#define DEG_PAD 53248               // 13 scan blocks * 4096 items
#define SCAN_BLOCKS 13
#define COUNT_BLOCKS 586            // ceil(N_EDGES/1024), 4 edges/thread
#define WSPLIT_BLOCKS 16            // 4096 fragment uint4s / 256
#define U_BLOCKS 2                  // 384 u-outputs / 256
#define SCORE_BLOCKS 198            // ceil((N_NODES+N_RELS)/256)
#define GEMM_BLOCKS 782             // ceil(N_NODES/64)

// ---------------- device scratch ----------------
__device__ __align__(16) int g_deg[DEG_PAD];
__device__ __align__(16) int g_off[DEG_PAD];     // exclusive prefix (padded; [N_NODES] valid)
__device__ int   g_scan_pub[SCAN_BLOCKS];        // inclusive+1; 0 = not ready
__device__ __align__(16) float g_u[3 * D];       // collapsed attention vector
__device__ float g_s_src[N_NODES];
__device__ float g_s_dst[N_NODES];
__device__ float g_s_rel[N_RELS];
__device__ __align__(8) uint2 g_edge[N_EDGES];   // {exp(score) bits, src}, grouped by dst
// W^T in HMMA b-fragment order: [ntile(16)][ks(8)][lane(32)] = {bhi0,bhi1,blo0,blo1}
__device__ __align__(16) uint4 g_wfrag[16 * 8 * 32];

// ---------------- HMMA m16n8k16 bf16, fp32 acc ----------------
#define MMA16816(d, a, b0, b1)                                                  \
    asm volatile("mma.sync.aligned.m16n8k16.row.col.f32.bf16.bf16.f32 "         \
        "{%0,%1,%2,%3}, {%4,%5,%6,%7}, {%8,%9}, {%0,%1,%2,%3};"                 \
        : "+f"((d)[0]), "+f"((d)[1]), "+f"((d)[2]), "+f"((d)[3])                \
        : "r"((a)[0]), "r"((a)[1]), "r"((a)[2]), "r"((a)[3]),                   \
          "r"(b0), "r"(b1))

#define LDSM4(r, a)                                                             \
    asm volatile("ldmatrix.sync.aligned.m8n8.x4.shared.b16 {%0,%1,%2,%3}, [%4];" \
        : "=r"((r)[0]), "=r"((r)[1]), "=r"((r)[2]), "=r"((r)[3]) : "r"(a))

__device__ __forceinline__ unsigned smem_u32(const void* p) {
    unsigned a;
    asm("{ .reg .u64 t; cvta.to.shared.u64 t, %1; cvt.u32.u64 %0, t; }" : "=r"(a) : "l"(p));
    return a;
}
__device__ __forceinline__ unsigned pack_hi(float a, float b) {
    __nv_bfloat162 v = __floats2bfloat162_rn(a, b);
    return *(unsigned*)&v;
}

// ============================================================================
// K1: degree count + W fragment-split + u-compute + scan-flag reset.
// ============================================================================
__global__ void k_prep(const float* __restrict__ W,
                       const float* __restrict__ w2,
                       const int*   __restrict__ edst,
                       const float* __restrict__ loopW) {
    if (blockIdx.x < COUNT_BLOCKS) {
        int i4 = blockIdx.x * 256 + threadIdx.x;
        if (i4 * 4 < N_EDGES) {
            int4 d4 = ((const int4*)edst)[i4];
            atomicAdd(&g_deg[d4.x], 1);
            atomicAdd(&g_deg[d4.y], 1);
            atomicAdd(&g_deg[d4.z], 1);
            atomicAdd(&g_deg[d4.w], 1);
        }
    } else if (blockIdx.x < COUNT_BLOCKS + WSPLIT_BLOCKS) {
        // W -> HMMA b-fragment table (+ scan-flag reset)
        int gid = (blockIdx.x - COUNT_BLOCKS) * 256 + threadIdx.x;
        if (gid < SCAN_BLOCKS) g_scan_pub[gid] = 0;
        int ntile = gid >> 8;            // 0..15
        int ks    = (gid >> 5) & 7;      // 0..7
        int lane  = gid & 31;
        int g = lane >> 2, t = lane & 3;
        int n  = ntile * 8 + g;
        int k0 = ks * 16 + 2 * t;
        float w00 = loopW[k0 * D + n];
        float w01 = loopW[(k0 + 1) * D + n];
        float w80 = loopW[(k0 + 8) * D + n];
        float w81 = loopW[(k0 + 9) * D + n];
        unsigned hi0 = pack_hi(w00, w01);
        unsigned hi1 = pack_hi(w80, w81);
        __nv_bfloat162 h0 = *(__nv_bfloat162*)&hi0;
        __nv_bfloat162 h1 = *(__nv_bfloat162*)&hi1;
        unsigned lo0 = pack_hi(w00 - __bfloat162float(__low2bfloat16(h0)),
                               w01 - __bfloat162float(__high2bfloat16(h0)));
        unsigned lo1 = pack_hi(w80 - __bfloat162float(__low2bfloat16(h1)),
                               w81 - __bfloat162float(__high2bfloat16(h1)));
        g_wfrag[gid] = make_uint4(hi0, hi1, lo0, lo1);
    } else {
        // u = attn_fc_w.T @ attn_fc2_w  (384 outputs, computed once)
        int i = (blockIdx.x - COUNT_BLOCKS - WSPLIT_BLOCKS) * 256 + threadIdx.x;
        if (i < 3 * D) {
            float s = 0.f;
            #pragma unroll 16
            for (int o = 0; o < D; o++) s += w2[o] * W[o * (3 * D) + i];
            g_u[i] = s;
        }
    }
}

// ============================================================================
// K2: co-launched scan (blocks [0,13)) and node/rel scalar scores (rest).
//   256-thread blocks for full-chip spread (211 blocks > 148 SMs).
// ============================================================================
__global__ void __launch_bounds__(256) k_scan_scores(const float* __restrict__ h,
                                                     const float* __restrict__ emb_rel) {
    if (blockIdx.x < SCAN_BLOCKS) {
        // ---- decoupled-lookback exclusive scan, 256 thr x 16 items ----
        __shared__ int sm[256];
        __shared__ int s_prefix;
        int b = blockIdx.x, t = threadIdx.x;
        int4 buf[4];
        int s = 0;
        #pragma unroll
        for (int i = 0; i < 4; i++) {
            buf[i] = ((const int4*)g_deg)[b * 1024 + t * 4 + i];
            s += buf[i].x + buf[i].y + buf[i].z + buf[i].w;
        }
        sm[t] = s;
        __syncthreads();
        #pragma unroll
        for (int off = 1; off < 256; off <<= 1) {
            int val = (t >= off) ? sm[t - off] : 0;
            __syncthreads();
            sm[t] += val;
            __syncthreads();
        }
        if (t == 255) {
            int inc = sm[255];
            int p = 0;
            if (b > 0) {
                volatile int* pub = g_scan_pub;
                int x;
                do { x = pub[b - 1]; } while (x == 0);
                p = x - 1;
            }
            ((volatile int*)g_scan_pub)[b] = p + inc + 1;
            s_prefix = p;
        }
        __syncthreads();
        int pre = s_prefix + sm[t] - s;
        #pragma unroll
        for (int i = 0; i < 4; i++) {
            int4 o;
            o.x = pre;              pre += buf[i].x;
            o.y = pre;              pre += buf[i].y;
            o.z = pre;              pre += buf[i].z;
            o.w = pre;              pre += buf[i].w;
            ((int4*)g_off)[b * 1024 + t * 4 + i] = o;
        }
    } else {
        // ---- scores: each warp handles 32 units; u loaded from global ----
        int t = threadIdx.x;
        int lane = t & 31;
        int wid  = t >> 5;
        float4 u0 = ((const float4*)g_u)[lane];        // u_s
        float4 u1 = ((const float4*)g_u)[32 + lane];   // u_t
        float4 u2 = ((const float4*)g_u)[64 + lane];   // u_r
        int base = ((blockIdx.x - SCAN_BLOCKS) * 8 + wid) * 32;
        #pragma unroll 4
        for (int i = 0; i < 32; i++) {
            int gw = base + i;
            if (gw < N_NODES) {
                float4 hv = ((const float4*)h)[gw * 32 + lane];
                float ss = hv.x * u0.x + hv.y * u0.y + hv.z * u0.z + hv.w * u0.w;
                float sd = hv.x * u1.x + hv.y * u1.y + hv.z * u1.z + hv.w * u1.w;
                #pragma unroll
                for (int o = 16; o; o >>= 1) {
                    ss += __shfl_xor_sync(0xffffffffu, ss, o);
                    sd += __shfl_xor_sync(0xffffffffu, sd, o);
                }
                if (lane == 0) { g_s_src[gw] = ss; g_s_dst[gw] = sd; }
            } else if (gw < N_NODES + N_RELS) {
                int r = gw - N_NODES;
                float4 rv = ((const float4*)emb_rel)[r * 32 + lane];
                float sr = rv.x * u2.x + rv.y * u2.y + rv.z * u2.z + rv.w * u2.w;
                #pragma unroll
                for (int o = 16; o; o >>= 1) sr += __shfl_xor_sync(0xffffffffu, sr, o);
                if (lane == 0) g_s_rel[r] = sr;
            }
        }
    }
}

// ============================================================================
// K3: MERGED independent work: HMMA GEMM tile (blocks [0,782)) and
//     edge fill (blocks [782, 782+586)). No dependence between the halves.
// ============================================================================
#define A_STRIDE 272                        // 17*16: 16B-aligned rows
#define SM_A_HI  0
#define SM_A_LO  (64 * A_STRIDE)            // 17408
#define GEMM_SMEM (2 * 64 * A_STRIDE)       // 34816

__global__ void __launch_bounds__(256) k_gemm_fill(const float* __restrict__ h,
                                                   float* __restrict__ out,
                                                   const int* __restrict__ esrc,
                                                   const int* __restrict__ edst,
                                                   const int* __restrict__ etype) {
    extern __shared__ char smc[];
    int tid = threadIdx.x;

    if (blockIdx.x >= GEMM_BLOCKS) {
        // ================= edge fill =================
        int i4 = (blockIdx.x - GEMM_BLOCKS) * 256 + tid;
        if (i4 * 4 >= N_EDGES) return;
        int4 s4 = ((const int4*)esrc)[i4];
        int4 d4 = ((const int4*)edst)[i4];
        int4 t4 = ((const int4*)etype)[i4];
        #pragma unroll
        for (int j = 0; j < 4; j++) {
            int s = (j == 0) ? s4.x : (j == 1) ? s4.y : (j == 2) ? s4.z : s4.w;
            int d = (j == 0) ? d4.x : (j == 1) ? d4.y : (j == 2) ? d4.z : d4.w;
            int r = (j == 0) ? t4.x : (j == 1) ? t4.y : (j == 2) ? t4.z : t4.w;
            float e = g_s_src[s] + g_s_dst[d] + g_s_rel[r];
            e = (e >= 0.f) ? e : 0.01f * e;
            int pos = g_off[d] + (atomicSub(&g_deg[d], 1) - 1);
            g_edge[pos] = make_uint2(__float_as_uint(__expf(e)), (unsigned)s);
        }
        return;
    }

    // ================= GEMM (round-7 validated path) =================
    unsigned sb = smem_u32(smc);
    int lane = tid & 31, wid = tid >> 5;
    int row0 = blockIdx.x * 64;

    #pragma unroll
    for (int i = 0; i < 8; i++) {
        int idx = tid + i * 256;
        int r = idx >> 5, c4 = idx & 31;
        int row = row0 + r;
        float4 v = (row < N_NODES) ? ((const float4*)h)[row * 32 + c4]
                                   : make_float4(0.f, 0.f, 0.f, 0.f);
        __nv_bfloat162 h01 = __floats2bfloat162_rn(v.x, v.y);
        __nv_bfloat162 h23 = __floats2bfloat162_rn(v.z, v.w);
        float lx = v.x - __bfloat162float(__low2bfloat16(h01));
        float ly = v.y - __bfloat162float(__high2bfloat16(h01));
        float lz = v.z - __bfloat162float(__low2bfloat16(h23));
        float lw = v.w - __bfloat162float(__high2bfloat16(h23));
        __nv_bfloat162 l01 = __floats2bfloat162_rn(lx, ly);
        __nv_bfloat162 l23 = __floats2bfloat162_rn(lz, lw);
        unsigned off = r * A_STRIDE + c4 * 8;
        *(uint2*)(smc + SM_A_HI + off) = make_uint2(*(unsigned*)&h01, *(unsigned*)&h23);
        *(uint2*)(smc + SM_A_LO + off) = make_uint2(*(unsigned*)&l01, *(unsigned*)&l23);
    }
    __syncthreads();

    int g = lane >> 2, t = lane & 3;
    int wm = (wid & 1) * 32;
    int wn = (wid >> 1) * 32;

    unsigned aAddr = sb + SM_A_HI + (wm + (lane & 15)) * A_STRIDE + (lane >> 4) * 16;
    const uint4* __restrict__ wf = g_wfrag + (wn >> 3) * 256 + lane;

    float acc[2][4][4];
    #pragma unroll
    for (int a = 0; a < 2; a++)
        #pragma unroll
        for (int b2 = 0; b2 < 4; b2++)
            #pragma unroll
            for (int c = 0; c < 4; c++) acc[a][b2][c] = 0.f;

    #pragma unroll
    for (int ks = 0; ks < 8; ks++) {
        unsigned ahi[2][4], alo[2][4];
        #pragma unroll
        for (int mt = 0; mt < 2; mt++) {
            unsigned addr = aAddr + mt * (16 * A_STRIDE) + ks * 32;
            LDSM4(ahi[mt], addr);
            LDSM4(alo[mt], addr + (unsigned)SM_A_LO);
        }
        #pragma unroll
        for (int nt = 0; nt < 4; nt++) {
            uint4 f = wf[nt * 256 + ks * 32];
            #pragma unroll
            for (int mt = 0; mt < 2; mt++) {
                MMA16816(acc[mt][nt], ahi[mt], f.x, f.y);
                MMA16816(acc[mt][nt], ahi[mt], f.z, f.w);
                MMA16816(acc[mt][nt], alo[mt], f.x, f.y);
            }
        }
    }

    #pragma unroll
    for (int mt = 0; mt < 2; mt++) {
        int r0 = row0 + wm + mt * 16 + g;
        #pragma unroll
        for (int nt = 0; nt < 4; nt++) {
            int col = wn + nt * 8 + 2 * t;
            if (r0 < N_NODES)
                *(float2*)(out + r0 * D + col) = make_float2(acc[mt][nt][0], acc[mt][nt][1]);
            if (r0 + 8 < N_NODES)
                *(float2*)(out + (r0 + 8) * D + col) = make_float2(acc[mt][nt][2], acc[mt][nt][3]);
        }
    }
}

// ============================================================================
// K4: per-dst softmax-weighted gather-sum (validated round-11/12 form).
// ============================================================================
__global__ void k_aggregate(const float* __restrict__ h, float* __restrict__ out) {
    int lane = threadIdx.x & 31;
    int n = blockIdx.x * 8 + (threadIdx.x >> 5);
    if (n >= N_NODES) return;
    int beg = g_off[n], end = g_off[n + 1];
    if (beg == end) return;

    float4 acc = {0.f, 0.f, 0.f, 0.f};
    float den = 0.f;
    int j = beg;
    for (; j + 4 <= end; j += 4) {
        uint2 e0 = g_edge[j],     e1 = g_edge[j + 1];
        uint2 e2 = g_edge[j + 2], e3 = g_edge[j + 3];
        float4 h0 = ((const float4*)h)[e0.y * 32 + lane];
        float4 h1 = ((const float4*)h)[e1.y * 32 + lane];
        float4 h2 = ((const float4*)h)[e2.y * 32 + lane];
        float4 h3 = ((const float4*)h)[e3.y * 32 + lane];
        float x0 = __uint_as_float(e0.x), x1 = __uint_as_float(e1.x);
        float x2 = __uint_as_float(e2.x), x3 = __uint_as_float(e3.x);
        den += (x0 + x1) + (x2 + x3);
        acc.x += x0 * h0.x + x1 * h1.x + x2 * h2.x + x3 * h3.x;
        acc.y += x0 * h0.y + x1 * h1.y + x2 * h2.y + x3 * h3.y;
        acc.z += x0 * h0.z + x1 * h1.z + x2 * h2.z + x3 * h3.z;
        acc.w += x0 * h0.w + x1 * h1.w + x2 * h2.w + x3 * h3.w;
    }
    for (; j < end; j++) {
        uint2 e0 = g_edge[j];
        float4 h0 = ((const float4*)h)[e0.y * 32 + lane];
        float x0 = __uint_as_float(e0.x);
        den += x0;
        acc.x += x0 * h0.x; acc.y += x0 * h0.y;
        acc.z += x0 * h0.z; acc.w += x0 * h0.w;
    }
    float inv = 1.f / den;
    float4* op = (float4*)out + n * 32 + lane;
    float4 o = *op;
    o.x += acc.x * inv; o.y += acc.y * inv;
    o.z += acc.z * inv; o.w += acc.w * inv;
    *op = o;
}

// ---------------- launch ----------------
extern "C" void kernel_launch(void* const* d_in, const int* in_sizes, int n_in,
                              void* d_out, int out_size) {
    const float* h          = (const float*)d_in[0];
    const float* emb_rel    = (const float*)d_in[1];
    const float* attn_fc_w  = (const float*)d_in[2];
    const float* attn_fc2_w = (const float*)d_in[3];
    const float* loop_w     = (const float*)d_in[4];
    const int*   esrc       = (const int*)d_in[5];
    const int*   edst       = (const int*)d_in[6];
    const int*   etype      = (const int*)d_in[7];
    float* out = (float*)d_out;

    cudaFuncSetAttribute(k_gemm_fill, cudaFuncAttributeMaxDynamicSharedMemorySize, GEMM_SMEM);

    k_prep<<<COUNT_BLOCKS + WSPLIT_BLOCKS + U_BLOCKS, 256>>>(attn_fc_w, attn_fc2_w, edst, loop_w);
    k_scan_scores<<<SCAN_BLOCKS + SCORE_BLOCKS, 256>>>(h, emb_rel);
    k_gemm_fill<<<GEMM_BLOCKS + COUNT_BLOCKS, 256, GEMM_SMEM>>>(h, out, esrc, edst, etype);
    k_aggregate<<<(N_NODES + 7) / 8, 256>>>(h, out);
}

// round 17
// speedup vs baseline: 1.1489x; 1.0298x over previous
#include <cuda_runtime.h>
#include <cuda_bf16.h>
#include <math.h>

#define N_NODES 50000
#define N_EDGES 600000
#define D 128
#define N_RELS 460

#define DEG_PAD 53248               // 13 scan blocks * 4096 items
#define SCAN_BLOCKS 13
#define COUNT_BLOCKS 293            // ceil(N_EDGES/2048), 8 edges/thread
#define FILL_BLOCKS 586             // ceil(N_EDGES/1024), 4 edges/thread
#define WSPLIT_BLOCKS 16            // 4096 fragment uint4s / 256
#define U_BLOCKS 2                  // 384 u-outputs / 256
#define SCORE_BLOCKS 198            // ceil((N_NODES+N_RELS)/256)
#define GEMM_BLOCKS 782             // ceil(N_NODES/64)

// ---------------- device scratch ----------------
__device__ __align__(16) int g_deg[DEG_PAD];
__device__ __align__(16) int g_off[DEG_PAD];     // exclusive prefix (padded; [N_NODES] valid)
__device__ int   g_scan_pub[SCAN_BLOCKS];        // inclusive+1; 0 = not ready
__device__ __align__(16) float g_u[3 * D];       // collapsed attention vector
__device__ float g_s_src[N_NODES];
__device__ float g_s_dst[N_NODES];
__device__ float g_s_rel[N_RELS];
__device__ __align__(8) uint2 g_edge[N_EDGES];   // {exp(score) bits, src}, grouped by dst
// W^T in HMMA b-fragment order: [ntile(16)][ks(8)][lane(32)] = {bhi0,bhi1,blo0,blo1}
__device__ __align__(16) uint4 g_wfrag[16 * 8 * 32];

// ---------------- HMMA m16n8k16 bf16, fp32 acc ----------------
#define MMA16816(d, a, b0, b1)                                                  \
    asm volatile("mma.sync.aligned.m16n8k16.row.col.f32.bf16.bf16.f32 "         \
        "{%0,%1,%2,%3}, {%4,%5,%6,%7}, {%8,%9}, {%0,%1,%2,%3};"                 \
        : "+f"((d)[0]), "+f"((d)[1]), "+f"((d)[2]), "+f"((d)[3])                \
        : "r"((a)[0]), "r"((a)[1]), "r"((a)[2]), "r"((a)[3]),                   \
          "r"(b0), "r"(b1))

#define LDSM4(r, a)                                                             \
    asm volatile("ldmatrix.sync.aligned.m8n8.x4.shared.b16 {%0,%1,%2,%3}, [%4];" \
        : "=r"((r)[0]), "=r"((r)[1]), "=r"((r)[2]), "=r"((r)[3]) : "r"(a))

__device__ __forceinline__ unsigned smem_u32(const void* p) {
    unsigned a;
    asm("{ .reg .u64 t; cvta.to.shared.u64 t, %1; cvt.u32.u64 %0, t; }" : "=r"(a) : "l"(p));
    return a;
}
__device__ __forceinline__ unsigned pack_hi(float a, float b) {
    __nv_bfloat162 v = __floats2bfloat162_rn(a, b);
    return *(unsigned*)&v;
}

// ============================================================================
// K1: degree count (8 edges/thread) + W fragment-split + u-compute + flag reset.
// ============================================================================
__global__ void k_prep(const float* __restrict__ W,
                       const float* __restrict__ w2,
                       const int*   __restrict__ edst,
                       const float* __restrict__ loopW) {
    if (blockIdx.x < COUNT_BLOCKS) {
        int i8 = blockIdx.x * 256 + threadIdx.x;      // 2 int4 groups per thread
        int base = i8 * 2;
        if (base * 4 < N_EDGES) {
            int4 a = ((const int4*)edst)[base];
            atomicAdd(&g_deg[a.x], 1);
            atomicAdd(&g_deg[a.y], 1);
            atomicAdd(&g_deg[a.z], 1);
            atomicAdd(&g_deg[a.w], 1);
            if ((base + 1) * 4 < N_EDGES) {
                int4 b = ((const int4*)edst)[base + 1];
                atomicAdd(&g_deg[b.x], 1);
                atomicAdd(&g_deg[b.y], 1);
                atomicAdd(&g_deg[b.z], 1);
                atomicAdd(&g_deg[b.w], 1);
            }
        }
    } else if (blockIdx.x < COUNT_BLOCKS + WSPLIT_BLOCKS) {
        // W -> HMMA b-fragment table (+ scan-flag reset)
        int gid = (blockIdx.x - COUNT_BLOCKS) * 256 + threadIdx.x;
        if (gid < SCAN_BLOCKS) g_scan_pub[gid] = 0;
        int ntile = gid >> 8;            // 0..15
        int ks    = (gid >> 5) & 7;      // 0..7
        int lane  = gid & 31;
        int g = lane >> 2, t = lane & 3;
        int n  = ntile * 8 + g;
        int k0 = ks * 16 + 2 * t;
        float w00 = loopW[k0 * D + n];
        float w01 = loopW[(k0 + 1) * D + n];
        float w80 = loopW[(k0 + 8) * D + n];
        float w81 = loopW[(k0 + 9) * D + n];
        unsigned hi0 = pack_hi(w00, w01);
        unsigned hi1 = pack_hi(w80, w81);
        __nv_bfloat162 h0 = *(__nv_bfloat162*)&hi0;
        __nv_bfloat162 h1 = *(__nv_bfloat162*)&hi1;
        unsigned lo0 = pack_hi(w00 - __bfloat162float(__low2bfloat16(h0)),
                               w01 - __bfloat162float(__high2bfloat16(h0)));
        unsigned lo1 = pack_hi(w80 - __bfloat162float(__low2bfloat16(h1)),
                               w81 - __bfloat162float(__high2bfloat16(h1)));
        g_wfrag[gid] = make_uint4(hi0, hi1, lo0, lo1);
    } else {
        // u = attn_fc_w.T @ attn_fc2_w  (384 outputs, computed once)
        int i = (blockIdx.x - COUNT_BLOCKS - WSPLIT_BLOCKS) * 256 + threadIdx.x;
        if (i < 3 * D) {
            float s = 0.f;
            #pragma unroll 16
            for (int o = 0; o < D; o++) s += w2[o] * W[o * (3 * D) + i];
            g_u[i] = s;
        }
    }
}

// ============================================================================
// K2: co-launched scan (blocks [0,13)) and node/rel scalar scores (rest).
//   256-thread blocks for full-chip spread (211 blocks > 148 SMs).
// ============================================================================
__global__ void __launch_bounds__(256) k_scan_scores(const float* __restrict__ h,
                                                     const float* __restrict__ emb_rel) {
    if (blockIdx.x < SCAN_BLOCKS) {
        // ---- decoupled-lookback exclusive scan, 256 thr x 16 items ----
        __shared__ int sm[256];
        __shared__ int s_prefix;
        int b = blockIdx.x, t = threadIdx.x;
        int4 buf[4];
        int s = 0;
        #pragma unroll
        for (int i = 0; i < 4; i++) {
            buf[i] = ((const int4*)g_deg)[b * 1024 + t * 4 + i];
            s += buf[i].x + buf[i].y + buf[i].z + buf[i].w;
        }
        sm[t] = s;
        __syncthreads();
        #pragma unroll
        for (int off = 1; off < 256; off <<= 1) {
            int val = (t >= off) ? sm[t - off] : 0;
            __syncthreads();
            sm[t] += val;
            __syncthreads();
        }
        if (t == 255) {
            int inc = sm[255];
            int p = 0;
            if (b > 0) {
                volatile int* pub = g_scan_pub;
                int x;
                do { x = pub[b - 1]; } while (x == 0);
                p = x - 1;
            }
            ((volatile int*)g_scan_pub)[b] = p + inc + 1;
            s_prefix = p;
        }
        __syncthreads();
        int pre = s_prefix + sm[t] - s;
        #pragma unroll
        for (int i = 0; i < 4; i++) {
            int4 o;
            o.x = pre;              pre += buf[i].x;
            o.y = pre;              pre += buf[i].y;
            o.z = pre;              pre += buf[i].z;
            o.w = pre;              pre += buf[i].w;
            ((int4*)g_off)[b * 1024 + t * 4 + i] = o;
        }
    } else {
        // ---- scores: each warp handles 32 units; u loaded from global ----
        int t = threadIdx.x;
        int lane = t & 31;
        int wid  = t >> 5;
        float4 u0 = ((const float4*)g_u)[lane];        // u_s
        float4 u1 = ((const float4*)g_u)[32 + lane];   // u_t
        float4 u2 = ((const float4*)g_u)[64 + lane];   // u_r
        int base = ((blockIdx.x - SCAN_BLOCKS) * 8 + wid) * 32;
        #pragma unroll 4
        for (int i = 0; i < 32; i++) {
            int gw = base + i;
            if (gw < N_NODES) {
                float4 hv = ((const float4*)h)[gw * 32 + lane];
                float ss = hv.x * u0.x + hv.y * u0.y + hv.z * u0.z + hv.w * u0.w;
                float sd = hv.x * u1.x + hv.y * u1.y + hv.z * u1.z + hv.w * u1.w;
                #pragma unroll
                for (int o = 16; o; o >>= 1) {
                    ss += __shfl_xor_sync(0xffffffffu, ss, o);
                    sd += __shfl_xor_sync(0xffffffffu, sd, o);
                }
                if (lane == 0) { g_s_src[gw] = ss; g_s_dst[gw] = sd; }
            } else if (gw < N_NODES + N_RELS) {
                int r = gw - N_NODES;
                float4 rv = ((const float4*)emb_rel)[r * 32 + lane];
                float sr = rv.x * u2.x + rv.y * u2.y + rv.z * u2.z + rv.w * u2.w;
                #pragma unroll
                for (int o = 16; o; o >>= 1) sr += __shfl_xor_sync(0xffffffffu, sr, o);
                if (lane == 0) g_s_rel[r] = sr;
            }
        }
    }
}

// ============================================================================
// K3: MERGED independent work: edge fill FIRST (blocks [0,586)) then HMMA
//     GEMM tiles (blocks [586, 586+782)). Fill's L2/atomic work overlaps
//     GEMM's tensor work from wave 1.
// ============================================================================
#define A_STRIDE 272                        // 17*16: 16B-aligned rows
#define SM_A_HI  0
#define SM_A_LO  (64 * A_STRIDE)            // 17408
#define GEMM_SMEM (2 * 64 * A_STRIDE)       // 34816

__global__ void __launch_bounds__(256) k_gemm_fill(const float* __restrict__ h,
                                                   float* __restrict__ out,
                                                   const int* __restrict__ esrc,
                                                   const int* __restrict__ edst,
                                                   const int* __restrict__ etype) {
    extern __shared__ char smc[];
    int tid = threadIdx.x;

    if (blockIdx.x < FILL_BLOCKS) {
        // ================= edge fill =================
        int i4 = blockIdx.x * 256 + tid;
        if (i4 * 4 >= N_EDGES) return;
        int4 s4 = ((const int4*)esrc)[i4];
        int4 d4 = ((const int4*)edst)[i4];
        int4 t4 = ((const int4*)etype)[i4];
        #pragma unroll
        for (int j = 0; j < 4; j++) {
            int s = (j == 0) ? s4.x : (j == 1) ? s4.y : (j == 2) ? s4.z : s4.w;
            int d = (j == 0) ? d4.x : (j == 1) ? d4.y : (j == 2) ? d4.z : d4.w;
            int r = (j == 0) ? t4.x : (j == 1) ? t4.y : (j == 2) ? t4.z : t4.w;
            float e = g_s_src[s] + g_s_dst[d] + g_s_rel[r];
            e = (e >= 0.f) ? e : 0.01f * e;
            int pos = g_off[d] + (atomicSub(&g_deg[d], 1) - 1);
            g_edge[pos] = make_uint2(__float_as_uint(__expf(e)), (unsigned)s);
        }
        return;
    }

    // ================= GEMM (round-7 validated path) =================
    unsigned sb = smem_u32(smc);
    int lane = tid & 31, wid = tid >> 5;
    int row0 = (blockIdx.x - FILL_BLOCKS) * 64;

    #pragma unroll
    for (int i = 0; i < 8; i++) {
        int idx = tid + i * 256;
        int r = idx >> 5, c4 = idx & 31;
        int row = row0 + r;
        float4 v = (row < N_NODES) ? ((const float4*)h)[row * 32 + c4]
                                   : make_float4(0.f, 0.f, 0.f, 0.f);
        __nv_bfloat162 h01 = __floats2bfloat162_rn(v.x, v.y);
        __nv_bfloat162 h23 = __floats2bfloat162_rn(v.z, v.w);
        float lx = v.x - __bfloat162float(__low2bfloat16(h01));
        float ly = v.y - __bfloat162float(__high2bfloat16(h01));
        float lz = v.z - __bfloat162float(__low2bfloat16(h23));
        float lw = v.w - __bfloat162float(__high2bfloat16(h23));
        __nv_bfloat162 l01 = __floats2bfloat162_rn(lx, ly);
        __nv_bfloat162 l23 = __floats2bfloat162_rn(lz, lw);
        unsigned off = r * A_STRIDE + c4 * 8;
        *(uint2*)(smc + SM_A_HI + off) = make_uint2(*(unsigned*)&h01, *(unsigned*)&h23);
        *(uint2*)(smc + SM_A_LO + off) = make_uint2(*(unsigned*)&l01, *(unsigned*)&l23);
    }
    __syncthreads();

    int g = lane >> 2, t = lane & 3;
    int wm = (wid & 1) * 32;
    int wn = (wid >> 1) * 32;

    unsigned aAddr = sb + SM_A_HI + (wm + (lane & 15)) * A_STRIDE + (lane >> 4) * 16;
    const uint4* __restrict__ wf = g_wfrag + (wn >> 3) * 256 + lane;

    float acc[2][4][4];
    #pragma unroll
    for (int a = 0; a < 2; a++)
        #pragma unroll
        for (int b2 = 0; b2 < 4; b2++)
            #pragma unroll
            for (int c = 0; c < 4; c++) acc[a][b2][c] = 0.f;

    #pragma unroll
    for (int ks = 0; ks < 8; ks++) {
        unsigned ahi[2][4], alo[2][4];
        #pragma unroll
        for (int mt = 0; mt < 2; mt++) {
            unsigned addr = aAddr + mt * (16 * A_STRIDE) + ks * 32;
            LDSM4(ahi[mt], addr);
            LDSM4(alo[mt], addr + (unsigned)SM_A_LO);
        }
        #pragma unroll
        for (int nt = 0; nt < 4; nt++) {
            uint4 f = wf[nt * 256 + ks * 32];
            #pragma unroll
            for (int mt = 0; mt < 2; mt++) {
                MMA16816(acc[mt][nt], ahi[mt], f.x, f.y);
                MMA16816(acc[mt][nt], ahi[mt], f.z, f.w);
                MMA16816(acc[mt][nt], alo[mt], f.x, f.y);
            }
        }
    }

    #pragma unroll
    for (int mt = 0; mt < 2; mt++) {
        int r0 = row0 + wm + mt * 16 + g;
        #pragma unroll
        for (int nt = 0; nt < 4; nt++) {
            int col = wn + nt * 8 + 2 * t;
            if (r0 < N_NODES)
                *(float2*)(out + r0 * D + col) = make_float2(acc[mt][nt][0], acc[mt][nt][1]);
            if (r0 + 8 < N_NODES)
                *(float2*)(out + (r0 + 8) * D + col) = make_float2(acc[mt][nt][2], acc[mt][nt][3]);
        }
    }
}

// ============================================================================
// K4: per-dst softmax-weighted gather-sum, 8-deep gather unroll (MLP 8).
// ============================================================================
__global__ void k_aggregate(const float* __restrict__ h, float* __restrict__ out) {
    int lane = threadIdx.x & 31;
    int n = blockIdx.x * 8 + (threadIdx.x >> 5);
    if (n >= N_NODES) return;
    int beg = g_off[n], end = g_off[n + 1];
    if (beg == end) return;

    float4 acc = {0.f, 0.f, 0.f, 0.f};
    float den = 0.f;
    int j = beg;
    for (; j + 8 <= end; j += 8) {
        uint2 e[8];
        #pragma unroll
        for (int q = 0; q < 8; q++) e[q] = g_edge[j + q];
        float4 hv[8];
        #pragma unroll
        for (int q = 0; q < 8; q++) hv[q] = ((const float4*)h)[e[q].y * 32 + lane];
        #pragma unroll
        for (int q = 0; q < 8; q++) {
            float x = __uint_as_float(e[q].x);
            den += x;
            acc.x += x * hv[q].x; acc.y += x * hv[q].y;
            acc.z += x * hv[q].z; acc.w += x * hv[q].w;
        }
    }
    for (; j + 4 <= end; j += 4) {
        uint2 e0 = g_edge[j],     e1 = g_edge[j + 1];
        uint2 e2 = g_edge[j + 2], e3 = g_edge[j + 3];
        float4 h0 = ((const float4*)h)[e0.y * 32 + lane];
        float4 h1 = ((const float4*)h)[e1.y * 32 + lane];
        float4 h2 = ((const float4*)h)[e2.y * 32 + lane];
        float4 h3 = ((const float4*)h)[e3.y * 32 + lane];
        float x0 = __uint_as_float(e0.x), x1 = __uint_as_float(e1.x);
        float x2 = __uint_as_float(e2.x), x3 = __uint_as_float(e3.x);
        den += (x0 + x1) + (x2 + x3);
        acc.x += x0 * h0.x + x1 * h1.x + x2 * h2.x + x3 * h3.x;
        acc.y += x0 * h0.y + x1 * h1.y + x2 * h2.y + x3 * h3.y;
        acc.z += x0 * h0.z + x1 * h1.z + x2 * h2.z + x3 * h3.z;
        acc.w += x0 * h0.w + x1 * h1.w + x2 * h2.w + x3 * h3.w;
    }
    for (; j < end; j++) {
        uint2 e0 = g_edge[j];
        float4 h0 = ((const float4*)h)[e0.y * 32 + lane];
        float x0 = __uint_as_float(e0.x);
        den += x0;
        acc.x += x0 * h0.x; acc.y += x0 * h0.y;
        acc.z += x0 * h0.z; acc.w += x0 * h0.w;
    }
    float inv = 1.f / den;
    float4* op = (float4*)out + n * 32 + lane;
    float4 o = *op;
    o.x += acc.x * inv; o.y += acc.y * inv;
    o.z += acc.z * inv; o.w += acc.w * inv;
    *op = o;
}

// ---------------- launch ----------------
extern "C" void kernel_launch(void* const* d_in, const int* in_sizes, int n_in,
                              void* d_out, int out_size) {
    const float* h          = (const float*)d_in[0];
    const float* emb_rel    = (const float*)d_in[1];
    const float* attn_fc_w  = (const float*)d_in[2];
    const float* attn_fc2_w = (const float*)d_in[3];
    const float* loop_w     = (const float*)d_in[4];
    const int*   esrc       = (const int*)d_in[5];
    const int*   edst       = (const int*)d_in[6];
    const int*   etype      = (const int*)d_in[7];
    float* out = (float*)d_out;

    cudaFuncSetAttribute(k_gemm_fill, cudaFuncAttributeMaxDynamicSharedMemorySize, GEMM_SMEM);

    k_prep<<<COUNT_BLOCKS + WSPLIT_BLOCKS + U_BLOCKS, 256>>>(attn_fc_w, attn_fc2_w, edst, loop_w);
    k_scan_scores<<<SCAN_BLOCKS + SCORE_BLOCKS, 256>>>(h, emb_rel);
    k_gemm_fill<<<FILL_BLOCKS + GEMM_BLOCKS, 256, GEMM_SMEM>>>(h, out, esrc, edst, etype);
    k_aggregate<<<(N_NODES + 7) / 8, 256>>>(h, out);
}